// round 2
// baseline (speedup 1.0000x reference)
#include <cuda_runtime.h>
#include <math.h>

// Problem constants (fixed by reference: IMG=2048, strides 8/16/32, B=2, M=128)
#define L3 65536
#define L4 16384
#define L5 4096
#define LTOT (L3 + L4 + L5)   // 86016
#define NB 2
#define NGT 128

__global__ __launch_bounds__(256) void fcos_kernel(
    const float* __restrict__ locs3,
    const float* __restrict__ locs4,
    const float* __restrict__ locs5,
    const float* __restrict__ gt,      // (B, 128, 5)
    const float* __restrict__ p3,      // (B, L3, 4)
    const float* __restrict__ p4,
    const float* __restrict__ p5,
    float* __restrict__ out)           // (B, LTOT, 9)
{
    __shared__ float sx0[NGT], sy0[NGT], sx1[NGT], sy1[NGT], ssc[NGT];

    const int i   = blockIdx.x * blockDim.x + threadIdx.x;  // 0 .. B*LTOT-1
    const int b   = i / LTOT;
    const int loc = i - b * LTOT;

    // Load this batch's GT boxes into shared memory (block is batch-uniform:
    // LTOT = 86016 is a multiple of 256).
    if (threadIdx.x < NGT) {
        const float* g = gt + ((size_t)b * NGT + threadIdx.x) * 5;
        const float x0 = g[0], y0 = g[1], x1 = g[2], y1 = g[3];
        sx0[threadIdx.x] = x0;
        sy0[threadIdx.x] = y0;
        sx1[threadIdx.x] = x1;
        sy1[threadIdx.x] = y1;
        ssc[threadIdx.x] = 1e8f - (x1 - x0) * (y1 - y0);   // mm value when ok
    }
    __syncthreads();

    // Level selection — uniform per block (65536, 16384, 4096 all % 256 == 0).
    float stride, lo, hi;
    const float* locs;
    const float* pred;
    int lidx;
    if (loc < L3) {
        stride = 8.0f;  lo = 0.0f;   hi = 64.0f;
        locs = locs3; pred = p3 + (size_t)b * L3 * 4; lidx = loc;
    } else if (loc < L3 + L4) {
        stride = 16.0f; lo = 64.0f;  hi = 128.0f;
        locs = locs4; pred = p4 + (size_t)b * L4 * 4; lidx = loc - L3;
    } else {
        stride = 32.0f; lo = 128.0f; hi = INFINITY;
        locs = locs5; pred = p5 + (size_t)b * L5 * 4; lidx = loc - (L3 + L4);
    }

    const float x = locs[lidx * 2 + 0];
    const float y = locs[lidx * 2 + 1];

    // Argmax over mm = ok * (1e8 - area). Strict ">" replicates jnp.argmax
    // first-occurrence semantics (all mm >= 0, init best=0, bi=0).
    float best = 0.0f;
    int   bi   = 0;
    #pragma unroll 4
    for (int j = 0; j < NGT; ++j) {
        const float a  = x - sx0[j];
        const float t  = y - sy0[j];
        const float r  = sx1[j] - x;
        const float bt = sy1[j] - y;
        const float pmin = fminf(fminf(a, t), fminf(r, bt));
        const float pmax = fmaxf(fmaxf(a, t), fmaxf(r, bt));
        const bool ok = (pmin > 0.0f) && (pmax > lo) && (pmax < hi);
        const float sc = ok ? ssc[j] : 0.0f;
        if (sc > best) { best = sc; bi = j; }
    }

    float d0, d1, d2, d3, ctr;
    if (best < 1e-5f) {
        d0 = d1 = d2 = d3 = -1.0f;
        ctr = -1.0f;
    } else {
        d0 = (x - sx0[bi]) / stride;
        d1 = (y - sy0[bi]) / stride;
        d2 = (sx1[bi] - x) / stride;
        d3 = (sy1[bi] - y) / stride;
        const float lrmin = fminf(d0, d2), lrmax = fmaxf(d0, d2);
        const float tbmin = fminf(d1, d3), tbmax = fmaxf(d1, d3);
        const float ratio = fminf(lrmin, tbmin) / (fmaxf(lrmax, tbmax) + 1e-6f);
        ctr = sqrtf(fmaxf(ratio, 0.0f));
    }

    // Decode predicted deltas.
    const float4 p = reinterpret_cast<const float4*>(pred)[lidx];
    const float dc0 = fmaxf(p.x, 0.0f);
    const float dc1 = fmaxf(p.y, 0.0f);
    const float dc2 = fmaxf(p.z, 0.0f);
    const float dc3 = fmaxf(p.w, 0.0f);
    const float bx1 = fmaxf(x - dc0 * stride, 0.0f);
    const float by1 = fmaxf(y - dc1 * stride, 0.0f);
    const float bx2 = fmaxf(x + dc2 * stride, 0.0f);
    const float by2 = fmaxf(y + dc3 * stride, 0.0f);

    float* o = out + (size_t)i * 9;
    o[0] = d0; o[1] = d1; o[2] = d2; o[3] = d3;
    o[4] = ctr;
    o[5] = bx1; o[6] = by1; o[7] = bx2; o[8] = by2;
}

extern "C" void kernel_launch(void* const* d_in, const int* in_sizes, int n_in,
                              void* d_out, int out_size) {
    const float* locs3 = (const float*)d_in[0];
    const float* locs4 = (const float*)d_in[1];
    const float* locs5 = (const float*)d_in[2];
    const float* gt    = (const float*)d_in[3];
    const float* p3    = (const float*)d_in[4];
    const float* p4    = (const float*)d_in[5];
    const float* p5    = (const float*)d_in[6];
    float* out = (float*)d_out;

    const int total = NB * LTOT;       // 172032
    const int threads = 256;
    const int blocks = total / threads; // 672, exact
    fcos_kernel<<<blocks, threads>>>(locs3, locs4, locs5, gt, p3, p4, p5, out);
}

// round 3
// speedup vs baseline: 1.2811x; 1.2811x over previous
#include <cuda_runtime.h>
#include <math.h>

// Problem constants (fixed by reference: IMG=2048, strides 8/16/32, B=2, M=128)
#define L3 65536
#define L4 16384
#define L5 4096
#define LTOT (L3 + L4 + L5)   // 86016
#define NB 2
#define NGT 128

// Per-location winner key: (float_bits(mm) << 32) | (127 - j).
// mm = 1e8f - area (always in [9.5e7, 1e8] when a box matches), positive float
// bits are order-isomorphic, so u64 max == argmax(mm) with first-index ties.
static __device__ unsigned long long g_keys[NB * LTOT];

// ---------------------------------------------------------------- kernel 1
__global__ __launch_bounds__(256) void k_init() {
    int i = blockIdx.x * 256 + threadIdx.x;
    g_keys[i] = 0ull;   // grid sized exactly NB*LTOT
}

// ---------------------------------------------------------------- kernel 2
// One warp per (batch, level, box): rasterize the pruned candidate cell range
// and atomicMax the packed key into each matching location slot.
__global__ __launch_bounds__(256) void k_scatter(
    const float* __restrict__ locs3,
    const float* __restrict__ locs4,
    const float* __restrict__ locs5,
    const float* __restrict__ gt)
{
    const int gw   = blockIdx.x * 8 + (threadIdx.x >> 5);  // 0..767
    const int lane = threadIdx.x & 31;
    const int b    = gw / 384;
    const int rem  = gw - b * 384;
    const int lvl  = rem >> 7;        // 0..2
    const int j    = rem & 127;

    const float* g = gt + ((size_t)(b * NGT + j)) * 5;
    const float x0 = g[0], y0 = g[1], x1 = g[2], y1 = g[3];

    float s, lo, hi; const float* locs; int n, off;
    if (lvl == 0)      { s = 8.f;  lo = 0.f;   hi = 64.f;     locs = locs3; n = 256; off = 0; }
    else if (lvl == 1) { s = 16.f; lo = 64.f;  hi = 128.f;    locs = locs4; n = 128; off = L3; }
    else               { s = 32.f; lo = 128.f; hi = INFINITY; locs = locs5; n = 64;  off = L3 + L4; }

    // pmax<hi needs l<hi && r<hi (and same in y): valid center range
    // x in (max(x0, x1-hi), min(x1, x0+hi)). Empty for wide boxes at low levels.
    const float xl = fmaxf(x0, x1 - hi), xh = fminf(x1, x0 + hi);
    const float yl = fmaxf(y0, y1 - hi), yh = fminf(y1, y0 + hi);
    if (xh <= xl || yh <= yl) return;

    int ix0 = max(0,     (int)floorf(xl / s - 0.5f));
    int ix1 = min(n - 1, (int)ceilf (xh / s));
    int iy0 = max(0,     (int)floorf(yl / s - 0.5f));
    int iy1 = min(n - 1, (int)ceilf (yh / s));
    const int nx = ix1 - ix0 + 1, ny = iy1 - iy0 + 1;
    if (nx <= 0 || ny <= 0) return;

    const float mmv = 1e8f - (x1 - x0) * (y1 - y0);
    const unsigned long long key =
        ((unsigned long long)__float_as_uint(mmv) << 32) | (unsigned)(127 - j);

    unsigned long long* base = g_keys + (size_t)b * LTOT + off;

    const int total = nx * ny;
    for (int c = lane; c < total; c += 32) {
        const int ix = ix0 + c % nx;
        const int iy = iy0 + c / nx;
        const int p  = iy * n + ix;
        const float x = locs[2 * p];       // exact same values the reference uses
        const float y = locs[2 * p + 1];
        const float l  = x - x0,  t  = y - y0;
        const float r  = x1 - x,  bt = y1 - y;
        const float pmin = fminf(fminf(l, t), fminf(r, bt));
        const float pmax = fmaxf(fmaxf(l, t), fmaxf(r, bt));
        if (pmin > 0.f && pmax > lo && pmax < hi)
            atomicMax(base + p, key);
    }
}

// ---------------------------------------------------------------- kernel 3
__global__ __launch_bounds__(256) void k_final(
    const float* __restrict__ locs3,
    const float* __restrict__ locs4,
    const float* __restrict__ locs5,
    const float* __restrict__ gt,
    const float* __restrict__ p3,
    const float* __restrict__ p4,
    const float* __restrict__ p5,
    float* __restrict__ out)
{
    const int i   = blockIdx.x * 256 + threadIdx.x;   // 0 .. NB*LTOT-1
    const int b   = i / LTOT;
    const int loc = i - b * LTOT;

    // Level selection — uniform per 256-thread block (all boundaries % 256 == 0).
    float stride;
    const float* locs;
    const float* pred;
    int lidx;
    if (loc < L3) {
        stride = 8.0f;  locs = locs3; pred = p3 + (size_t)b * L3 * 4; lidx = loc;
    } else if (loc < L3 + L4) {
        stride = 16.0f; locs = locs4; pred = p4 + (size_t)b * L4 * 4; lidx = loc - L3;
    } else {
        stride = 32.0f; locs = locs5; pred = p5 + (size_t)b * L5 * 4; lidx = loc - (L3 + L4);
    }

    const float x = locs[lidx * 2 + 0];
    const float y = locs[lidx * 2 + 1];

    const unsigned long long key = g_keys[i];

    float d0, d1, d2, d3, ctr;
    if (key == 0ull) {
        d0 = d1 = d2 = d3 = -1.0f;
        ctr = -1.0f;
    } else {
        const int j = 127 - (int)(key & 0xFFFFFFFFu);
        const float* g = gt + ((size_t)(b * NGT + j)) * 5;
        const float x0 = g[0], y0 = g[1], x1 = g[2], y1 = g[3];
        d0 = (x - x0) / stride;
        d1 = (y - y0) / stride;
        d2 = (x1 - x) / stride;
        d3 = (y1 - y) / stride;
        const float lrmin = fminf(d0, d2), lrmax = fmaxf(d0, d2);
        const float tbmin = fminf(d1, d3), tbmax = fmaxf(d1, d3);
        const float ratio = fminf(lrmin, tbmin) / (fmaxf(lrmax, tbmax) + 1e-6f);
        ctr = sqrtf(fmaxf(ratio, 0.0f));
    }

    // Decode predicted deltas.
    const float4 p = reinterpret_cast<const float4*>(pred)[lidx];
    const float dc0 = fmaxf(p.x, 0.0f);
    const float dc1 = fmaxf(p.y, 0.0f);
    const float dc2 = fmaxf(p.z, 0.0f);
    const float dc3 = fmaxf(p.w, 0.0f);
    const float bx1 = fmaxf(x - dc0 * stride, 0.0f);
    const float by1 = fmaxf(y - dc1 * stride, 0.0f);
    const float bx2 = fmaxf(x + dc2 * stride, 0.0f);
    const float by2 = fmaxf(y + dc3 * stride, 0.0f);

    float* o = out + (size_t)i * 9;
    o[0] = d0; o[1] = d1; o[2] = d2; o[3] = d3;
    o[4] = ctr;
    o[5] = bx1; o[6] = by1; o[7] = bx2; o[8] = by2;
}

extern "C" void kernel_launch(void* const* d_in, const int* in_sizes, int n_in,
                              void* d_out, int out_size) {
    const float* locs3 = (const float*)d_in[0];
    const float* locs4 = (const float*)d_in[1];
    const float* locs5 = (const float*)d_in[2];
    const float* gt    = (const float*)d_in[3];
    const float* p3    = (const float*)d_in[4];
    const float* p4    = (const float*)d_in[5];
    const float* p5    = (const float*)d_in[6];
    float* out = (float*)d_out;

    const int total = NB * LTOT;          // 172032
    k_init<<<total / 256, 256>>>();
    k_scatter<<<96, 256>>>(locs3, locs4, locs5, gt);   // 768 warps
    k_final<<<total / 256, 256>>>(locs3, locs4, locs5, gt, p3, p4, p5, out);
}

// round 4
// speedup vs baseline: 1.8045x; 1.4085x over previous
#include <cuda_runtime.h>
#include <math.h>

// Problem constants (fixed by reference: IMG=2048, strides 8/16/32, B=2, M=128)
#define L3 65536
#define L4 16384
#define L5 4096
#define LTOT (L3 + L4 + L5)   // 86016
#define NB 2
#define NGT 128

// Single fused kernel:
//  1) block-level prune: shortlist of boxes whose valid y-interval intersects
//     this block's row range (block = 256 consecutive locations, which is
//     1/2/4 full grid rows at p3/p4/p5 — y is nondecreasing within a block)
//  2) per-thread scan of the shortlist with an order-independent packed key
//     (mm_bits<<32 | (127-j)<<8 | slot) replicating jnp.argmax tie-breaking
//  3) finalize: deltas, centerness, pred decode, store 9 floats.
__global__ __launch_bounds__(256) void fcos_fused(
    const float* __restrict__ locs3,
    const float* __restrict__ locs4,
    const float* __restrict__ locs5,
    const float* __restrict__ gt,      // (B, 128, 5)
    const float* __restrict__ p3,      // (B, L3, 4)
    const float* __restrict__ p4,
    const float* __restrict__ p5,
    float* __restrict__ out)           // (B, LTOT, 9)
{
    __shared__ float sx0[NGT], sy0[NGT], sx1[NGT], sy1[NGT], smm[NGT];
    __shared__ int   sj[NGT];
    __shared__ int   scnt;
    __shared__ float sylo, syhi;

    const int tid = threadIdx.x;
    const int i   = blockIdx.x * 256 + tid;          // 0 .. NB*LTOT-1
    const int b   = i / LTOT;
    const int loc = i - b * LTOT;

    // Level selection — uniform per block (65536, 81920, 86016 all % 256 == 0).
    float stride, lo, hi;
    const float* locs;
    const float* pred;
    int lidx;
    if (loc < L3) {
        stride = 8.0f;  lo = 0.0f;   hi = 64.0f;
        locs = locs3; pred = p3 + (size_t)b * L3 * 4; lidx = loc;
    } else if (loc < L3 + L4) {
        stride = 16.0f; lo = 64.0f;  hi = 128.0f;
        locs = locs4; pred = p4 + (size_t)b * L4 * 4; lidx = loc - L3;
    } else {
        stride = 32.0f; lo = 128.0f; hi = INFINITY;
        locs = locs5; pred = p5 + (size_t)b * L5 * 4; lidx = loc - (L3 + L4);
    }

    const float2 xy = reinterpret_cast<const float2*>(locs)[lidx];
    const float x = xy.x, y = xy.y;

    // Block y-range (y nondecreasing with lidx inside a block: row-major grid).
    if (tid == 0)   { scnt = 0; sylo = y; }
    if (tid == 255) { syhi = y; }
    __syncthreads();
    const float ylo = sylo, yhi = syhi;

    // Build shortlist: box j is a candidate iff its valid x-interval is
    // nonempty and its valid y-interval intersects [ylo, yhi].
    if (tid < NGT) {
        const float* g = gt + ((size_t)(b * NGT + tid)) * 5;
        const float x0 = g[0], y0 = g[1], x1 = g[2], y1 = g[3];
        const float xl = fmaxf(x0, x1 - hi), xh = fminf(x1, x0 + hi);
        const float yl = fmaxf(y0, y1 - hi), yh = fminf(y1, y0 + hi);
        if (xh > xl && yh > ylo && yl < yhi) {
            const int s = atomicAdd(&scnt, 1);
            sx0[s] = x0; sy0[s] = y0; sx1[s] = x1; sy1[s] = y1;
            smm[s] = 1e8f - (x1 - x0) * (y1 - y0);
            sj[s]  = tid;
        }
    }
    __syncthreads();
    const int S = scnt;

    // Scan shortlist with order-independent packed key.
    unsigned long long best = 0ull;
    for (int s = 0; s < S; ++s) {
        const float l  = x - sx0[s];
        const float t  = y - sy0[s];
        const float r  = sx1[s] - x;
        const float bt = sy1[s] - y;
        const float pmin = fminf(fminf(l, t), fminf(r, bt));
        const float pmax = fmaxf(fmaxf(l, t), fmaxf(r, bt));
        if (pmin > 0.0f && pmax > lo && pmax < hi) {
            const unsigned long long key =
                ((unsigned long long)__float_as_uint(smm[s]) << 32) |
                ((unsigned)(NGT - 1 - sj[s]) << 8) | (unsigned)s;
            if (key > best) best = key;
        }
    }

    float d0, d1, d2, d3, ctr;
    if (best == 0ull) {
        d0 = d1 = d2 = d3 = -1.0f;
        ctr = -1.0f;
    } else {
        const int s = (int)(best & 0xFFu);
        d0 = (x - sx0[s]) / stride;
        d1 = (y - sy0[s]) / stride;
        d2 = (sx1[s] - x) / stride;
        d3 = (sy1[s] - y) / stride;
        const float lrmin = fminf(d0, d2), lrmax = fmaxf(d0, d2);
        const float tbmin = fminf(d1, d3), tbmax = fmaxf(d1, d3);
        const float ratio = fminf(lrmin, tbmin) / (fmaxf(lrmax, tbmax) + 1e-6f);
        ctr = sqrtf(fmaxf(ratio, 0.0f));
    }

    // Decode predicted deltas.
    const float4 p = reinterpret_cast<const float4*>(pred)[lidx];
    const float dc0 = fmaxf(p.x, 0.0f);
    const float dc1 = fmaxf(p.y, 0.0f);
    const float dc2 = fmaxf(p.z, 0.0f);
    const float dc3 = fmaxf(p.w, 0.0f);
    const float bx1 = fmaxf(x - dc0 * stride, 0.0f);
    const float by1 = fmaxf(y - dc1 * stride, 0.0f);
    const float bx2 = fmaxf(x + dc2 * stride, 0.0f);
    const float by2 = fmaxf(y + dc3 * stride, 0.0f);

    float* o = out + (size_t)i * 9;
    o[0] = d0; o[1] = d1; o[2] = d2; o[3] = d3;
    o[4] = ctr;
    o[5] = bx1; o[6] = by1; o[7] = bx2; o[8] = by2;
}

extern "C" void kernel_launch(void* const* d_in, const int* in_sizes, int n_in,
                              void* d_out, int out_size) {
    const float* locs3 = (const float*)d_in[0];
    const float* locs4 = (const float*)d_in[1];
    const float* locs5 = (const float*)d_in[2];
    const float* gt    = (const float*)d_in[3];
    const float* p3    = (const float*)d_in[4];
    const float* p4    = (const float*)d_in[5];
    const float* p5    = (const float*)d_in[6];
    float* out = (float*)d_out;

    const int total = NB * LTOT;          // 172032
    fcos_fused<<<total / 256, 256>>>(locs3, locs4, locs5, gt, p3, p4, p5, out);
}